// round 2
// baseline (speedup 1.0000x reference)
#include <cuda_runtime.h>
#include <cstdint>

// ============================================================================
// CgpHmmCell: HMM forward scan. B=128, T=8192, S=512, M=64.
//
// Linear-domain rescaled recurrence (exactly the reference math):
//   F_0[b][s] = (s==0) ? E_0[b][0]+eps : 0 ;  C_0 = 0
//   step t:    M = max_s F_{t-1}[b][s] ;  C += log(M)  (Kahan)
//              y[b][j]   = sum_s F_{t-1}[b][s] * A[s][j]
//              F_t[b][j] = (E_t[b][j]+eps) * (y * (1/M) + eps)
//   alpha_T = log(F_T) + C
//   loglik  = log(sum_s F_T/M_T + S*eps) + log(M_T) + C
//
// 16 teams x 8-CTA clusters. Each CTA: 64-column A slice in smem, computes its
// F slice for 8 batches, replicates F via DSMEM pushes + cluster.sync.
// ============================================================================

#define T_LEN 8192
#define EPS   1e-16f

// smem float offsets
#define OFF_FB   32768   // fbuf[2][8][512]
#define OFF_PART 40960   // part[32][512]
#define OFF_MAXB 57344   // maxb[8 src][8 b]
#define OFF_INVM 57408
#define OFF_CV   57416
#define OFF_CK   57424
#define SMEM_FLOATS 57432
#define SMEM_BYTES  (SMEM_FLOATS * 4)   // 229728 <= 232448 opt-in

__device__ unsigned char g_sym[128 * T_LEN];

// ---------------------------------------------------------------------------
// Prepass: sym[b][t] = argmax_m x[b][t][m]  (one warp per (b,t), one-hot input)
// ---------------------------------------------------------------------------
__global__ void sym_kernel(const float* __restrict__ x) {
    int gw   = (blockIdx.x * blockDim.x + threadIdx.x) >> 5;
    int lane = threadIdx.x & 31;
    if (gw >= 128 * T_LEN) return;
    const float* p = x + (size_t)gw * 64;
    unsigned m1 = __ballot_sync(0xffffffffu, p[lane] > 0.5f);
    unsigned m2 = __ballot_sync(0xffffffffu, p[lane + 32] > 0.5f);
    if (lane == 0)
        g_sym[gw] = (unsigned char)(m1 ? (__ffs(m1) - 1) : (31 + __ffs(m2)));
}

// ---------------------------------------------------------------------------
// helpers
// ---------------------------------------------------------------------------
__device__ __forceinline__ uint32_t smem_u32(const void* p) {
    uint32_t a;
    asm("{ .reg .u64 t; cvta.to.shared.u64 t, %1; cvt.u32.u64 %0, t; }"
        : "=r"(a) : "l"(p));
    return a;
}
__device__ __forceinline__ uint32_t mapa_u32(uint32_t a, uint32_t r) {
    uint32_t o;
    asm("mapa.shared::cluster.u32 %0, %1, %2;" : "=r"(o) : "r"(a), "r"(r));
    return o;
}
__device__ __forceinline__ void stc_f32(uint32_t a, float v) {
    asm volatile("st.shared::cluster.f32 [%0], %1;" :: "r"(a), "f"(v) : "memory");
}
__device__ __forceinline__ void cluster_arrive() {
    asm volatile("barrier.cluster.arrive.aligned;" ::: "memory");
}
__device__ __forceinline__ void cluster_wait() {
    asm volatile("barrier.cluster.wait.aligned;" ::: "memory");
}

// ---------------------------------------------------------------------------
// Main persistent scan kernel
// ---------------------------------------------------------------------------
__global__ void __launch_bounds__(512, 1) __cluster_dims__(8, 1, 1)
hmm_kernel(const float* __restrict__ A, const float* __restrict__ Bm,
           float* __restrict__ out, int out_size) {
    extern __shared__ float sm[];
    float* fb   = sm + OFF_FB;
    float* part = sm + OFF_PART;
    float* maxb = sm + OFF_MAXB;
    float* invM = sm + OFF_INVM;
    float* Cv   = sm + OFF_CV;
    float* Ck   = sm + OFF_CK;

    int tid = threadIdx.x;
    uint32_t rank;
    asm("mov.u32 %0, %%cluster_ctarank;" : "=r"(rank));
    int team = blockIdx.x >> 3;

    // ---- load A slice: As[s][64] = A[s][rank*64 + j] ----
    for (int i = tid; i < 512 * 64; i += 512) {
        int s = i >> 6, j = i & 63;
        sm[i] = A[s * 512 + (rank << 6) + j];
    }
    // ---- init F0, C, maxbuf seed ----
    for (int i = tid; i < 4096; i += 512) fb[i] = 0.0f;
    if (tid < 8) {
        int bglob = team * 8 + tid;
        float e0 = Bm[(int)g_sym[(size_t)bglob * T_LEN] * 512] + EPS;
        fb[tid * 512] = e0;                          // F0[b][0]
        #pragma unroll
        for (int c = 0; c < 8; ++c) maxb[c * 8 + tid] = (c == 0) ? e0 : 0.0f;
        invM[tid] = 0.0f; Cv[tid] = 0.0f; Ck[tid] = 0.0f;
    }
    __syncthreads();
    cluster_arrive(); cluster_wait();        // all CTAs initialized

    // peer smem bases (cluster-window address arithmetic is offset-linear)
    uint32_t base = smem_u32(sm);
    uint32_t pb[8];
    #pragma unroll
    for (int c = 0; c < 8; ++c) pb[c] = mapa_u32(base, c);

    // finalize-phase identity: one output (b, j) per thread
    int ob = tid >> 6;                        // local batch 0..7
    int oj = tid & 63;                        // local j 0..63
    int bglob = team * 8 + ob;
    const unsigned char* symrow = g_sym + (size_t)bglob * T_LEN;
    const float* Bcol = Bm + (rank << 6) + oj;

    // MAC identity
    int jg = tid & 7, bg = (tid >> 3) & 1, kg = tid >> 4;

    for (int t = 1; t < T_LEN; ++t) {
        // prefetch E_t[b][j] = B[sym][rank*64+j]  (L1-hot; consumed ~4k cyc later)
        float e = Bcol[(int)symrow[t] * 512];

        // invM + Kahan C update from previous step's maxes
        if (tid < 8) {
            float M = maxb[tid];
            #pragma unroll
            for (int c = 1; c < 8; ++c) M = fmaxf(M, maxb[c * 8 + tid]);
            invM[tid] = 1.0f / M;
            float yv = logf(M) - Ck[tid];
            float tt = Cv[tid] + yv;
            Ck[tid] = (tt - Cv[tid]) - yv;
            Cv[tid] = tt;
        }
        __syncthreads();

        // ---- MAC: acc[bi][u] = sum over 16 s of F[b][s]*A[s][j] ----
        const float* Frd  = fb + ((t + 1) & 1) * 4096 + bg * 2048 + kg * 16;
        const float* Arow = sm + kg * 16 * 64 + jg * 4;
        float acc[4][8];
        #pragma unroll
        for (int bi = 0; bi < 4; ++bi)
            #pragma unroll
            for (int u = 0; u < 8; ++u) acc[bi][u] = 0.0f;

        #pragma unroll 4
        for (int si = 0; si < 16; ++si) {
            float4 a0 = *(const float4*)(Arow + si * 64);
            float4 a1 = *(const float4*)(Arow + si * 64 + 32);
            float fv[4];
            #pragma unroll
            for (int bi = 0; bi < 4; ++bi) fv[bi] = Frd[bi * 512 + si];
            #pragma unroll
            for (int bi = 0; bi < 4; ++bi) {
                acc[bi][0] += fv[bi] * a0.x;  acc[bi][1] += fv[bi] * a0.y;
                acc[bi][2] += fv[bi] * a0.z;  acc[bi][3] += fv[bi] * a0.w;
                acc[bi][4] += fv[bi] * a1.x;  acc[bi][5] += fv[bi] * a1.y;
                acc[bi][6] += fv[bi] * a1.z;  acc[bi][7] += fv[bi] * a1.w;
            }
        }

        // ---- stage partials: part[kg][(bg*4+bi)*64 + jcol] ----
        float* prow = part + kg * 512 + bg * 256 + jg * 4;
        #pragma unroll
        for (int bi = 0; bi < 4; ++bi) {
            *(float4*)(prow + bi * 64) =
                make_float4(acc[bi][0], acc[bi][1], acc[bi][2], acc[bi][3]);
            *(float4*)(prow + bi * 64 + 32) =
                make_float4(acc[bi][4], acc[bi][5], acc[bi][6], acc[bi][7]);
        }
        __syncthreads();

        // ---- reduce 32 partials, finalize, broadcast to cluster ----
        float s0 = 0, s1 = 0, s2 = 0, s3 = 0;
        const float* pc = part + tid;
        #pragma unroll
        for (int k = 0; k < 32; k += 4) {
            s0 += pc[k * 512];        s1 += pc[(k + 1) * 512];
            s2 += pc[(k + 2) * 512];  s3 += pc[(k + 3) * 512];
        }
        float y = (s0 + s1) + (s2 + s3);
        float fnew = (e + EPS) * (y * invM[ob] + EPS);

        uint32_t fidx = (uint32_t)(OFF_FB + (t & 1) * 4096 + ob * 512 +
                                   (rank << 6) + oj);
        fb[fidx - OFF_FB + OFF_FB - OFF_FB + (t & 1) * 0] = fnew; // placate none
        sm[fidx] = fnew;                                   // local copy
        uint32_t rel = fidx * 4u;
        #pragma unroll
        for (int c = 0; c < 8; ++c)
            if (c != rank) stc_f32(pb[c] + rel, fnew);
        __syncthreads();

        // ---- local slice max -> push to all maxbufs ----
        if (tid < 8) {
            const float* fr = fb + (t & 1) * 4096 + tid * 512 + (rank << 6);
            float m0 = fr[0], m1 = fr[1], m2 = fr[2], m3 = fr[3];
            #pragma unroll
            for (int j2 = 4; j2 < 64; j2 += 4) {
                m0 = fmaxf(m0, fr[j2]);     m1 = fmaxf(m1, fr[j2 + 1]);
                m2 = fmaxf(m2, fr[j2 + 2]); m3 = fmaxf(m3, fr[j2 + 3]);
            }
            float mx = fmaxf(fmaxf(m0, m1), fmaxf(m2, m3));
            uint32_t midx = (uint32_t)(OFF_MAXB + rank * 8 + tid);
            sm[midx] = mx;
            uint32_t mrel = midx * 4u;
            #pragma unroll
            for (int c = 0; c < 8; ++c)
                if (c != rank) stc_f32(pb[c] + mrel, mx);
        }
        cluster_arrive();
        cluster_wait();
    }

    // ---- epilogue: alpha_T ----
    float Fv = fb[4096 + ob * 512 + (rank << 6) + oj];   // final buf = (8191&1)=1
    float alpha = logf(Fv) + Cv[ob];
    if (out_size >= 65536)
        out[(size_t)bglob * 512 + (rank << 6) + oj] = alpha;

    // ---- loglik (rank 0 of each team) ----
    if (rank == 0) {
        int w = tid >> 5, lane = tid & 31;
        if (w < 8) {
            int b = w;
            const float* fr = fb + 4096 + b * 512;
            float sum = 0.0f;
            for (int s = lane; s < 512; s += 32) sum += fr[s];
            #pragma unroll
            for (int off = 16; off; off >>= 1)
                sum += __shfl_xor_sync(0xffffffffu, sum, off);
            if (lane == 0) {
                float M = maxb[b];
                #pragma unroll
                for (int c = 1; c < 8; ++c) M = fmaxf(M, maxb[c * 8 + b]);
                float ll = logf(sum / M + 512.0f * EPS) + logf(M) + Cv[b];
                if (out_size >= 65664)      out[65536 + team * 8 + b] = ll;
                else if (out_size == 128)   out[team * 8 + b] = ll;
            }
        }
    }
}

// ---------------------------------------------------------------------------
extern "C" void kernel_launch(void* const* d_in, const int* in_sizes, int n_in,
                              void* d_out, int out_size) {
    // identify inputs by element count (x=67108864, A=262144, B=32768)
    const float* x = nullptr; const float* A = nullptr; const float* Bm = nullptr;
    for (int i = 0; i < n_in; ++i) {
        if (in_sizes[i] == 128 * T_LEN * 64)      x  = (const float*)d_in[i];
        else if (in_sizes[i] == 512 * 512)        A  = (const float*)d_in[i];
        else if (in_sizes[i] == 64 * 512)         Bm = (const float*)d_in[i];
    }
    if (!x)  x  = (const float*)d_in[0];
    if (!A)  A  = (const float*)d_in[1];
    if (!Bm) Bm = (const float*)d_in[2];

    cudaFuncSetAttribute(hmm_kernel,
                         cudaFuncAttributeMaxDynamicSharedMemorySize,
                         SMEM_BYTES);

    sym_kernel<<<(128 * T_LEN) / 8, 256>>>(x);
    hmm_kernel<<<128, 512, SMEM_BYTES>>>(A, Bm, (float*)d_out, out_size);
}

// round 3
// speedup vs baseline: 1.1247x; 1.1247x over previous
#include <cuda_runtime.h>
#include <cstdint>

// ============================================================================
// CgpHmmCell: HMM forward scan. B=128, T=8192, S=512, M=64.
//
// Linear-domain rescaled recurrence (exactly the reference math):
//   F_0[b][s] = (s==0) ? E_0[b][0]+eps : 0 ;  C_0 = 0
//   step t:    M = max_s F_{t-1}[b][s] ;  C += log(M)  (Kahan)
//              y[b][j]   = sum_s F_{t-1}[b][s] * A[s][j]
//              F_t[b][j] = (E_t[b][j]+eps) * (y * (1/M) + eps)
//   alpha_T = log(F_T) + C ;  loglik = log(sum F_T/M_T + S*eps) + log(M_T) + C
//
// 16 teams x 8-CTA clusters; A 64-col slice per CTA in smem; F replicated via
// DSMEM st.b64 pushes; fma.rn.f32x2 MAC; 1 bar.sync + 1 cluster.sync per step.
// ============================================================================

#define T_LEN 8192
#define EPS   1e-16f

typedef unsigned long long ull;

// smem float offsets
#define FSTRIDE  514                 // padded batch stride (bank fix)
#define FBUF     4112                // 8 * 514
#define OFF_FB   32768               // fb[2][8][514]
#define OFF_PART 40992               // part[32][512]
#define OFF_MAXB 57376               // maxb[2][16][8]  (parity, src=cta*2+half, b)
#define OFF_INVM 57632
#define OFF_CV   57640
#define OFF_CK   57648
#define SMEM_FLOATS 57656
#define SMEM_BYTES  (SMEM_FLOATS * 4)   // 230624 <= 232448

__device__ unsigned char g_sym[128 * T_LEN];

// ---------------------------------------------------------------------------
__global__ void sym_kernel(const float* __restrict__ x) {
    int gw   = (blockIdx.x * blockDim.x + threadIdx.x) >> 5;
    int lane = threadIdx.x & 31;
    if (gw >= 128 * T_LEN) return;
    const float* p = x + (size_t)gw * 64;
    unsigned m1 = __ballot_sync(0xffffffffu, p[lane] > 0.5f);
    unsigned m2 = __ballot_sync(0xffffffffu, p[lane + 32] > 0.5f);
    if (lane == 0)
        g_sym[gw] = (unsigned char)(m1 ? (__ffs(m1) - 1) : (31 + __ffs(m2)));
}

// ---------------------------------------------------------------------------
__device__ __forceinline__ uint32_t smem_u32(const void* p) {
    uint32_t a;
    asm("{ .reg .u64 t; cvta.to.shared.u64 t, %1; cvt.u32.u64 %0, t; }"
        : "=r"(a) : "l"(p));
    return a;
}
__device__ __forceinline__ uint32_t mapa_u32(uint32_t a, uint32_t r) {
    uint32_t o;
    asm("mapa.shared::cluster.u32 %0, %1, %2;" : "=r"(o) : "r"(a), "r"(r));
    return o;
}
__device__ __forceinline__ void stc_f32(uint32_t a, float v) {
    asm volatile("st.shared::cluster.f32 [%0], %1;" :: "r"(a), "f"(v) : "memory");
}
__device__ __forceinline__ void stc_b64(uint32_t a, ull v) {
    asm volatile("st.shared::cluster.b64 [%0], %1;" :: "r"(a), "l"(v) : "memory");
}
__device__ __forceinline__ void cluster_arrive() {
    asm volatile("barrier.cluster.arrive.aligned;" ::: "memory");
}
__device__ __forceinline__ void cluster_wait() {
    asm volatile("barrier.cluster.wait.aligned;" ::: "memory");
}
#define FMA2(d, a, b) \
    asm("fma.rn.f32x2 %0, %1, %2, %0;" : "+l"(d) : "l"(a), "l"(b))
#define DUP2(d, f) \
    asm("mov.b64 %0, {%1, %1};" : "=l"(d) : "f"(f))

// ---------------------------------------------------------------------------
__global__ void __launch_bounds__(512, 1) __cluster_dims__(8, 1, 1)
hmm_kernel(const float* __restrict__ A, const float* __restrict__ Bm,
           float* __restrict__ out, int out_size) {
    extern __shared__ float sm[];
    float* fb   = sm + OFF_FB;
    float* part = sm + OFF_PART;
    float* maxb = sm + OFF_MAXB;
    float* invM = sm + OFF_INVM;
    float* Cv   = sm + OFF_CV;
    float* Ck   = sm + OFF_CK;

    int tid = threadIdx.x;
    uint32_t rank;
    asm("mov.u32 %0, %%cluster_ctarank;" : "=r"(rank));
    int team = blockIdx.x >> 3;

    // ---- load A slice: As[s][64] = A[s][rank*64 + j] ----
    for (int i = tid; i < 512 * 64; i += 512) {
        int s = i >> 6, j = i & 63;
        sm[i] = A[s * 512 + (rank << 6) + j];
    }
    // ---- init F buffers, maxb, C ----
    for (int i = tid; i < 2 * FBUF; i += 512) fb[i] = 0.0f;
    for (int i = tid; i < 256; i += 512) maxb[i] = 0.0f;
    __syncthreads();
    if (tid < 8) {
        int bglob = team * 8 + tid;
        float e0 = Bm[(int)g_sym[(size_t)bglob * T_LEN] * 512] + EPS;
        fb[tid * FSTRIDE] = e0;                 // F0[b][0], buffer 0
        maxb[0 * 8 + tid] = e0;                 // parity 0, src 0 (cta0 half0)
        invM[tid] = 0.0f; Cv[tid] = 0.0f; Ck[tid] = 0.0f;
    }
    __syncthreads();
    cluster_arrive(); cluster_wait();

    uint32_t base = smem_u32(sm);
    uint32_t pb[8];
    #pragma unroll
    for (int c = 0; c < 8; ++c) pb[c] = mapa_u32(base, c);

    // output identity: one (b, j) per thread
    int ob = tid >> 6, oj = tid & 63;
    int wid = tid >> 5, lane = tid & 31;
    int bglob = team * 8 + ob;
    const unsigned char* symrow = g_sym + (size_t)bglob * T_LEN;
    const float* Bcol = Bm + (rank << 6) + oj;

    // MAC identity
    int jg = tid & 7, bg = (tid >> 3) & 1, kg = tid >> 4;

    float fnew = 0.0f;
    for (int t = 1; t < T_LEN; ++t) {
        // E prefetch (consumed in finalize, several thousand cycles later)
        float e = Bcol[(int)symrow[t] * 512];

        // invM + Kahan C update (warp 0 only; overlaps MAC — ordered by the
        // staging barrier before its consumers, and by the previous cluster
        // barrier after the previous finalize readers)
        if (tid < 8) {
            const float* mb = maxb + (((t - 1) & 1) << 7);
            float M = mb[tid];
            #pragma unroll
            for (int s2 = 1; s2 < 16; ++s2) M = fmaxf(M, mb[s2 * 8 + tid]);
            invM[tid] = 1.0f / M;
            float yv = logf(M) - Ck[tid];
            float tt = Cv[tid] + yv;
            Ck[tid] = (tt - Cv[tid]) - yv;
            Cv[tid] = tt;
        }

        // ---- MAC with fma.rn.f32x2: acc over 16 s values ----
        const float* Frd  = fb + (((t + 1) & 1) ? FBUF : 0) + bg * (4 * FSTRIDE)
                          + (kg << 4);
        const float* Arow = sm + (kg << 10) + (jg << 2);
        ull acc[4][4];
        #pragma unroll
        for (int bi = 0; bi < 4; ++bi)
            #pragma unroll
            for (int u = 0; u < 4; ++u) acc[bi][u] = 0ull;

        #pragma unroll
        for (int sp = 0; sp < 8; ++sp) {
            const float* ar = Arow + (sp << 7);           // rows 2sp, 2sp+1
            ulonglong2 A0  = *(const ulonglong2*)(ar);
            ulonglong2 A0h = *(const ulonglong2*)(ar + 32);
            ulonglong2 A1  = *(const ulonglong2*)(ar + 64);
            ulonglong2 A1h = *(const ulonglong2*)(ar + 96);
            #pragma unroll
            for (int bi = 0; bi < 4; ++bi) {
                float2 f2 = *(const float2*)(Frd + bi * FSTRIDE + (sp << 1));
                ull flo, fhi;
                DUP2(flo, f2.x);
                DUP2(fhi, f2.y);
                FMA2(acc[bi][0], A0.x,  flo);
                FMA2(acc[bi][1], A0.y,  flo);
                FMA2(acc[bi][2], A0h.x, flo);
                FMA2(acc[bi][3], A0h.y, flo);
                FMA2(acc[bi][0], A1.x,  fhi);
                FMA2(acc[bi][1], A1.y,  fhi);
                FMA2(acc[bi][2], A1h.x, fhi);
                FMA2(acc[bi][3], A1h.y, fhi);
            }
        }

        // ---- stage partials ----
        float* prow = part + (kg << 9) + (bg << 8) + (jg << 2);
        #pragma unroll
        for (int bi = 0; bi < 4; ++bi) {
            *(ulonglong2*)(prow + bi * 64)      = make_ulonglong2(acc[bi][0], acc[bi][1]);
            *(ulonglong2*)(prow + bi * 64 + 32) = make_ulonglong2(acc[bi][2], acc[bi][3]);
        }
        __syncthreads();

        // ---- reduce 32 partials, finalize ----
        float s0 = 0, s1 = 0, s2 = 0, s3 = 0;
        const float* pc = part + tid;
        #pragma unroll
        for (int k = 0; k < 32; k += 4) {
            s0 += pc[k * 512];        s1 += pc[(k + 1) * 512];
            s2 += pc[(k + 2) * 512];  s3 += pc[(k + 3) * 512];
        }
        float y = (s0 + s1) + (s2 + s3);
        fnew = (e + EPS) * (y * invM[ob] + EPS);

        // ---- push F pairs to all 8 CTAs (incl. self) ----
        float fhi_v = __shfl_down_sync(0xffffffffu, fnew, 1);
        uint32_t fidx = (uint32_t)(OFF_FB + ((t & 1) ? FBUF : 0)
                                   + ob * FSTRIDE + (rank << 6) + oj);
        if ((oj & 1) == 0) {
            ull pr;
            asm("mov.b64 %0, {%1, %2};" : "=l"(pr) : "f"(fnew), "f"(fhi_v));
            uint32_t rel = fidx << 2;
            #pragma unroll
            for (int c = 0; c < 8; ++c) stc_b64(pb[c] + rel, pr);
        }

        // ---- warp slice-max via shfl, lane0 pushes ----
        float wm = fnew;
        #pragma unroll
        for (int off = 16; off; off >>= 1)
            wm = fmaxf(wm, __shfl_xor_sync(0xffffffffu, wm, off));
        if (lane == 0) {
            int src = (int)(rank << 1) | (wid & 1);
            uint32_t midx = (uint32_t)(OFF_MAXB + ((t & 1) << 7)
                                       + src * 8 + (wid >> 1));
            uint32_t mrel = midx << 2;
            #pragma unroll
            for (int c = 0; c < 8; ++c) stc_f32(pb[c] + mrel, wm);
        }
        cluster_arrive();
        cluster_wait();
    }

    // ---- epilogue: alpha_T (final buffer = parity of t=8191 = 1) ----
    float alpha = logf(fnew) + Cv[ob];
    if (out_size >= 65536)
        out[(size_t)bglob * 512 + (rank << 6) + oj] = alpha;

    // ---- loglik (rank 0 of each team) ----
    if (rank == 0 && wid < 8) {
        int b = wid;
        const float* fr = fb + FBUF + b * FSTRIDE;
        float sum = 0.0f;
        for (int s = lane; s < 512; s += 32) sum += fr[s];
        #pragma unroll
        for (int off = 16; off; off >>= 1)
            sum += __shfl_xor_sync(0xffffffffu, sum, off);
        if (lane == 0) {
            const float* mb = maxb + 128;         // parity 1
            float M = mb[b];
            #pragma unroll
            for (int s2 = 1; s2 < 16; ++s2) M = fmaxf(M, mb[s2 * 8 + b]);
            float ll = logf(sum / M + 512.0f * EPS) + logf(M) + Cv[b];
            if (out_size >= 65664)      out[65536 + team * 8 + b] = ll;
            else if (out_size == 128)   out[team * 8 + b] = ll;
        }
    }
}

// ---------------------------------------------------------------------------
extern "C" void kernel_launch(void* const* d_in, const int* in_sizes, int n_in,
                              void* d_out, int out_size) {
    const float* x = nullptr; const float* A = nullptr; const float* Bm = nullptr;
    for (int i = 0; i < n_in; ++i) {
        if (in_sizes[i] == 128 * T_LEN * 64)      x  = (const float*)d_in[i];
        else if (in_sizes[i] == 512 * 512)        A  = (const float*)d_in[i];
        else if (in_sizes[i] == 64 * 512)         Bm = (const float*)d_in[i];
    }
    if (!x)  x  = (const float*)d_in[0];
    if (!A)  A  = (const float*)d_in[1];
    if (!Bm) Bm = (const float*)d_in[2];

    cudaFuncSetAttribute(hmm_kernel,
                         cudaFuncAttributeMaxDynamicSharedMemorySize,
                         SMEM_BYTES);

    sym_kernel<<<(128 * T_LEN) / 8, 256>>>(x);
    hmm_kernel<<<128, 512, SMEM_BYTES>>>(A, Bm, (float*)d_out, out_size);
}